// round 4
// baseline (speedup 1.0000x reference)
#include <cuda_runtime.h>
#include <math.h>

// Scratch (no cudaMalloc allowed): QK projection buffer and attention output.
__device__ float g_qk[33554432];   // 32768 x 1024  (cols 0..511 = Q, 512..1023 = K)
__device__ float g_ao[16777216];   // 32768 x 512   (attention output)

// ---------------------------------------------------------------------------
// C[M,N] = A[M,K] @ B[N,K]^T (+ bias). BM=BN=128, BK=16, 256 thr, 8x8 microtile.
// ---------------------------------------------------------------------------
template<bool BIAS>
__global__ __launch_bounds__(256, 2)
void sgemm_nt(const float* __restrict__ A, const float* __restrict__ B,
              const float* __restrict__ bias, float* __restrict__ C,
              int N, int K)
{
    __shared__ float As[16 * 128];
    __shared__ float Bs[16 * 128];

    const int tid = threadIdx.x;
    const int m0 = blockIdx.y * 128;
    const int n0 = blockIdx.x * 128;
    const int tr = tid >> 4;   // 0..15 -> rows tr*8..
    const int tc = tid & 15;   // 0..15 -> cols tc*8..

    float acc[8][8];
#pragma unroll
    for (int i = 0; i < 8; i++)
#pragma unroll
        for (int j = 0; j < 8; j++) acc[i][j] = 0.f;

    for (int k0 = 0; k0 < K; k0 += 16) {
#pragma unroll
        for (int l = 0; l < 2; l++) {
            int idx = tid + l * 256;          // 0..511
            int row = idx >> 2;               // 0..127
            int kq  = idx & 3;                // 4 float4 per row
            float4 va = *(const float4*)(A + (size_t)(m0 + row) * K + k0 + kq * 4);
            As[(kq * 4 + 0) * 128 + row] = va.x;
            As[(kq * 4 + 1) * 128 + row] = va.y;
            As[(kq * 4 + 2) * 128 + row] = va.z;
            As[(kq * 4 + 3) * 128 + row] = va.w;
            float4 vb = *(const float4*)(B + (size_t)(n0 + row) * K + k0 + kq * 4);
            Bs[(kq * 4 + 0) * 128 + row] = vb.x;
            Bs[(kq * 4 + 1) * 128 + row] = vb.y;
            Bs[(kq * 4 + 2) * 128 + row] = vb.z;
            Bs[(kq * 4 + 3) * 128 + row] = vb.w;
        }
        __syncthreads();
#pragma unroll
        for (int kk = 0; kk < 16; kk++) {
            float4 a0 = *(const float4*)&As[kk * 128 + tr * 8];
            float4 a1 = *(const float4*)&As[kk * 128 + tr * 8 + 4];
            float4 b0 = *(const float4*)&Bs[kk * 128 + tc * 8];
            float4 b1 = *(const float4*)&Bs[kk * 128 + tc * 8 + 4];
            float af[8] = {a0.x, a0.y, a0.z, a0.w, a1.x, a1.y, a1.z, a1.w};
            float bf[8] = {b0.x, b0.y, b0.z, b0.w, b1.x, b1.y, b1.z, b1.w};
#pragma unroll
            for (int i = 0; i < 8; i++)
#pragma unroll
                for (int j = 0; j < 8; j++)
                    acc[i][j] += af[i] * bf[j];
        }
        __syncthreads();
    }

#pragma unroll
    for (int i = 0; i < 8; i++) {
        size_t crow = (size_t)(m0 + tr * 8 + i) * N + n0 + tc * 8;
#pragma unroll
        for (int j = 0; j < 8; j += 4) {
            float4 v;
            v.x = acc[i][j + 0]; v.y = acc[i][j + 1];
            v.z = acc[i][j + 2]; v.w = acc[i][j + 3];
            if (BIAS) {
                v.x += bias[n0 + tc * 8 + j + 0];
                v.y += bias[n0 + tc * 8 + j + 1];
                v.z += bias[n0 + tc * 8 + j + 2];
                v.w += bias[n0 + tc * 8 + j + 3];
            }
            *(float4*)(C + crow + j) = v;
        }
    }
}

// ---------------------------------------------------------------------------
// Windowed attention. One CTA per (batch, window): 256 CTAs, 256 threads.
//   Phase A: S[128,256] = Q(128x512) . K2(256x512)^T  (K2 = prev||cur window K)
//   softmax with mask (j > i+128), P -> smem (128KB)
//   Phase C: O[128,512] = P . K2, tiled 64 output cols at a time.
// smem: Ps 32768 floats + Kc 16384 floats = 192KB dynamic.
// ---------------------------------------------------------------------------
__global__ __launch_bounds__(256, 1)
void attn_kernel(const float* __restrict__ qk, float* __restrict__ ao)
{
    extern __shared__ float sm[];
    float* Ps = sm;              // 128*256 floats
    float* Kc = sm + 32768;      // 256*64 floats (phase C)
    float* sQ = sm;              // phase A: 32*128 (overlaps Ps region, OK)
    float* sK = sm + 4096;       // phase A: 32*256

    const int tid = threadIdx.x;
    const int b   = blockIdx.x >> 6;
    const int wi  = blockIdx.x & 63;
    const size_t qrow0 = (size_t)b * 8192 + (size_t)wi * 128;
    const bool w0 = (wi == 0);
    const int tr = tid >> 4;     // 0..15
    const int tc = tid & 15;     // 0..15

    float acc[8][16];
#pragma unroll
    for (int i = 0; i < 8; i++)
#pragma unroll
        for (int j = 0; j < 16; j++) acc[i][j] = 0.f;

    // ---- Phase A: S = Q . K2^T over d chunks of 32 ----
    for (int d0 = 0; d0 < 512; d0 += 32) {
#pragma unroll
        for (int l = 0; l < 4; l++) {
            int idx = tid + l * 256;       // 0..1023
            int row = idx >> 3;            // 0..127
            int kq  = idx & 7;
            float4 v = *(const float4*)(qk + (qrow0 + row) * 1024 + d0 + kq * 4);
            sQ[(kq * 4 + 0) * 128 + row] = v.x;
            sQ[(kq * 4 + 1) * 128 + row] = v.y;
            sQ[(kq * 4 + 2) * 128 + row] = v.z;
            sQ[(kq * 4 + 3) * 128 + row] = v.w;
        }
#pragma unroll
        for (int l = 0; l < 8; l++) {
            int idx = tid + l * 256;       // 0..2047
            int row = idx >> 3;            // 0..255 (K2 row)
            int kq  = idx & 7;
            float4 v = make_float4(0.f, 0.f, 0.f, 0.f);
            if (!(w0 && row < 128))
                v = *(const float4*)(qk + (qrow0 + row - 128) * 1024 + 512 + d0 + kq * 4);
            sK[(kq * 4 + 0) * 256 + row] = v.x;
            sK[(kq * 4 + 1) * 256 + row] = v.y;
            sK[(kq * 4 + 2) * 256 + row] = v.z;
            sK[(kq * 4 + 3) * 256 + row] = v.w;
        }
        __syncthreads();
#pragma unroll 8
        for (int kk = 0; kk < 32; kk++) {
            float4 a0 = *(const float4*)&sQ[kk * 128 + tr * 8];
            float4 a1 = *(const float4*)&sQ[kk * 128 + tr * 8 + 4];
            float4 b0 = *(const float4*)&sK[kk * 256 + tc * 16];
            float4 b1 = *(const float4*)&sK[kk * 256 + tc * 16 + 4];
            float4 b2 = *(const float4*)&sK[kk * 256 + tc * 16 + 8];
            float4 b3 = *(const float4*)&sK[kk * 256 + tc * 16 + 12];
            float af[8]  = {a0.x, a0.y, a0.z, a0.w, a1.x, a1.y, a1.z, a1.w};
            float bf[16] = {b0.x, b0.y, b0.z, b0.w, b1.x, b1.y, b1.z, b1.w,
                            b2.x, b2.y, b2.z, b2.w, b3.x, b3.y, b3.z, b3.w};
#pragma unroll
            for (int i = 0; i < 8; i++)
#pragma unroll
                for (int j = 0; j < 16; j++)
                    acc[i][j] += af[i] * bf[j];
        }
        __syncthreads();
    }

    // ---- mask + softmax (rows live on 16-lane groups of same tr) ----
    const float scale = 0.04419417382415922f;   // 512^-0.5
#pragma unroll
    for (int ri = 0; ri < 8; ri++) {
        int i = tr * 8 + ri;
        float mx = -3.402823466e38f;
#pragma unroll
        for (int cj = 0; cj < 16; cj++) {
            int j = tc * 16 + cj;
            float v = acc[ri][cj] * scale;
            if (j > i + 128) v = -3.402823466e38f;
            acc[ri][cj] = v;
            mx = fmaxf(mx, v);
        }
#pragma unroll
        for (int m = 8; m >= 1; m >>= 1)
            mx = fmaxf(mx, __shfl_xor_sync(0xffffffffu, mx, m));
        float sum = 0.f;
#pragma unroll
        for (int cj = 0; cj < 16; cj++) {
            float e = __expf(acc[ri][cj] - mx);
            acc[ri][cj] = e;
            sum += e;
        }
#pragma unroll
        for (int m = 8; m >= 1; m >>= 1)
            sum += __shfl_xor_sync(0xffffffffu, sum, m);
        float inv = 1.f / sum;
#pragma unroll
        for (int cj = 0; cj < 16; cj++)
            Ps[i * 256 + tc * 16 + cj] = acc[ri][cj] * inv;
    }
    __syncthreads();

    // ---- Phase C: O = P . K2, 8 chunks of 64 output cols ----
    for (int co = 0; co < 8; co++) {
        int c0 = co * 64;
#pragma unroll
        for (int l = 0; l < 16; l++) {
            int idx = tid + l * 256;       // 0..4095
            int row = idx >> 4;            // 0..255
            int cq  = idx & 15;
            float4 v = make_float4(0.f, 0.f, 0.f, 0.f);
            if (!(w0 && row < 128))
                v = *(const float4*)(qk + (qrow0 + row - 128) * 1024 + 512 + c0 + cq * 4);
            *(float4*)&Kc[row * 64 + cq * 4] = v;
        }
        __syncthreads();

        float a2[8][4];
#pragma unroll
        for (int i = 0; i < 8; i++)
#pragma unroll
            for (int j = 0; j < 4; j++) a2[i][j] = 0.f;

#pragma unroll 2
        for (int j4 = 0; j4 < 64; j4++) {
            float4 bv0 = *(const float4*)&Kc[(j4 * 4 + 0) * 64 + tc * 4];
            float4 bv1 = *(const float4*)&Kc[(j4 * 4 + 1) * 64 + tc * 4];
            float4 bv2 = *(const float4*)&Kc[(j4 * 4 + 2) * 64 + tc * 4];
            float4 bv3 = *(const float4*)&Kc[(j4 * 4 + 3) * 64 + tc * 4];
#pragma unroll
            for (int ri = 0; ri < 8; ri++) {
                float4 a = *(const float4*)&Ps[(tr * 8 + ri) * 256 + j4 * 4];
                a2[ri][0] += a.x * bv0.x; a2[ri][1] += a.x * bv0.y;
                a2[ri][2] += a.x * bv0.z; a2[ri][3] += a.x * bv0.w;
                a2[ri][0] += a.y * bv1.x; a2[ri][1] += a.y * bv1.y;
                a2[ri][2] += a.y * bv1.z; a2[ri][3] += a.y * bv1.w;
                a2[ri][0] += a.z * bv2.x; a2[ri][1] += a.z * bv2.y;
                a2[ri][2] += a.z * bv2.z; a2[ri][3] += a.z * bv2.w;
                a2[ri][0] += a.w * bv3.x; a2[ri][1] += a.w * bv3.y;
                a2[ri][2] += a.w * bv3.z; a2[ri][3] += a.w * bv3.w;
            }
        }

#pragma unroll
        for (int ri = 0; ri < 8; ri++) {
            float4 v;
            v.x = a2[ri][0]; v.y = a2[ri][1]; v.z = a2[ri][2]; v.w = a2[ri][3];
            *(float4*)(ao + (qrow0 + tr * 8 + ri) * 512 + c0 + tc * 4) = v;
        }
        __syncthreads();
    }
}

// ---------------------------------------------------------------------------
extern "C" void kernel_launch(void* const* d_in, const int* in_sizes, int n_in,
                              void* d_out, int out_size)
{
    (void)in_sizes; (void)n_in; (void)out_size;
    const float* x     = (const float*)d_in[0];   // (4,8192,512)
    const float* w_qkv = (const float*)d_in[1];   // (1536,512); rows 0..1023 used
    const float* w_out = (const float*)d_in[2];   // (512,512)
    const float* b_out = (const float*)d_in[3];   // (512,)
    float* out = (float*)d_out;                   // (4,8192,512)

    float *qk = nullptr, *ao = nullptr;
    cudaGetSymbolAddress((void**)&qk, g_qk);
    cudaGetSymbolAddress((void**)&ao, g_ao);

    cudaFuncSetAttribute(attn_kernel,
                         cudaFuncAttributeMaxDynamicSharedMemorySize, 196608);

    // 1) QK projection (V is dead in the reference — skip it).
    dim3 g1(1024 / 128, 32768 / 128);
    sgemm_nt<false><<<g1, 256>>>(x, w_qkv, nullptr, qk, 1024, 512);

    // 2) Windowed attention (256 windows total).
    attn_kernel<<<256, 256, 196608>>>(qk, ao);

    // 3) Output projection + bias.
    dim3 g3(512 / 128, 32768 / 128);
    sgemm_nt<true><<<g3, 256>>>(ao, w_out, b_out, out, 512, 512);
}

// round 6
// speedup vs baseline: 1.9159x; 1.9159x over previous
#include <cuda_runtime.h>
#include <math.h>
#include <stdint.h>

// ---------------------------------------------------------------------------
// Scratch (no cudaMalloc allowed)
// ---------------------------------------------------------------------------
__device__ float g_qk[33554432];   // 32768 x 1024  (Q | K), fp32 GEMM1 output
__device__ float g_ao[16777216];   // 32768 x 512   attention output (tf32-rounded)
__device__ float g_xc[16777216];   // 32768 x 512   x rounded to tf32
__device__ float g_wc[524288];     // 1024 x 512    w_qkv rows 0..1023, tf32-rounded
__device__ float g_wo[262144];     // 512 x 512     w_out, tf32-rounded

__device__ __forceinline__ float rtf32(float v) {  // round-to-nearest tf32
    uint32_t r;
    asm("cvt.rna.tf32.f32 %0, %1;" : "=r"(r) : "f"(v));
    return __uint_as_float(r);
}
__device__ __forceinline__ void cpa16(uint32_t s, const void* g) {
    asm volatile("cp.async.cg.shared.global [%0], [%1], 16;" :: "r"(s), "l"(g));
}
__device__ __forceinline__ uint32_t smem_u32(const void* p) {
    uint32_t a;
    asm("{ .reg .u64 t; cvta.to.shared.u64 t, %1; cvt.u32.u64 %0, t; }"
        : "=r"(a) : "l"(p));
    return a;
}

// mma.sync m16n8k8 tf32 (baseline PTX, works on .target sm_103)
__device__ __forceinline__ void mma_tf32(float* d, const uint32_t* a,
                                         const uint32_t* b) {
    asm volatile(
        "mma.sync.aligned.m16n8k8.row.col.f32.tf32.tf32.f32 "
        "{%0,%1,%2,%3}, {%4,%5,%6,%7}, {%8,%9}, {%0,%1,%2,%3};"
        : "+f"(d[0]), "+f"(d[1]), "+f"(d[2]), "+f"(d[3])
        : "r"(a[0]), "r"(a[1]), "r"(a[2]), "r"(a[3]), "r"(b[0]), "r"(b[1]));
}

// ---------------------------------------------------------------------------
// tf32 mma.sync GEMM: C[M,N] = A[M,K] @ B[N,K]^T (+bias).
// CTA: 128x128 tile, 128 threads = 4 warps (2x2), warp tile 64x64.
// K chunks of 32, double-buffered cp.async. Smem rows padded to 44 floats
// (176B: 16B-aligned, conflict-free for fragment LDS pattern).
// Dynamic smem: 4 * 128 * 44 * 4B = 90112 B.
// ---------------------------------------------------------------------------
#define TSTRIDE 44

__device__ __forceinline__ void load_tile44(float* dst, const float* gsrc,
                                            int K, int tid) {
#pragma unroll
    for (int l = 0; l < 8; l++) {
        int idx = tid + l * 128;        // 0..1023 (128 rows x 8 x 16B)
        int row = idx >> 3;
        int k16 = idx & 7;
        cpa16(smem_u32(dst + row * TSTRIDE + k16 * 4),
              gsrc + (size_t)row * K + k16 * 4);
    }
}

template<bool BIAS>
__global__ __launch_bounds__(128)
void mma_gemm(const float* __restrict__ A, const float* __restrict__ B,
              const float* __restrict__ bias, float* __restrict__ C,
              int N, int K)
{
    extern __shared__ float sm[];
    float* Abuf[2] = {sm,          sm + 5632};
    float* Bbuf[2] = {sm + 11264,  sm + 16896};

    const int tid = threadIdx.x;
    const int wid = tid >> 5, lid = tid & 31;
    const int gid = lid >> 2, tig = lid & 3;     // groupID, thread-in-group
    const int wm = wid >> 1, wn = wid & 1;       // 2x2 warp grid
    const int n0 = blockIdx.x * 128, m0 = blockIdx.y * 128;
    const int NC = K >> 5;

    const float* gA = A + (size_t)m0 * K;
    const float* gB = B + (size_t)n0 * K;

    float acc[4][8][4];
#pragma unroll
    for (int mt = 0; mt < 4; mt++)
#pragma unroll
        for (int nt = 0; nt < 8; nt++)
#pragma unroll
            for (int r = 0; r < 4; r++) acc[mt][nt][r] = 0.f;

    load_tile44(Abuf[0], gA, K, tid);
    load_tile44(Bbuf[0], gB, K, tid);
    asm volatile("cp.async.commit_group;" ::: "memory");

    for (int c = 0; c < NC; c++) {
        if (c + 1 < NC) {
            int nb = (c + 1) & 1;
            load_tile44(Abuf[nb], gA + (c + 1) * 32, K, tid);
            load_tile44(Bbuf[nb], gB + (c + 1) * 32, K, tid);
            asm volatile("cp.async.commit_group;" ::: "memory");
            asm volatile("cp.async.wait_group 1;" ::: "memory");
        } else {
            asm volatile("cp.async.wait_group 0;" ::: "memory");
        }
        __syncthreads();                    // chunk c visible to all

        const float* As = Abuf[c & 1];
        const float* Bs = Bbuf[c & 1];
#pragma unroll
        for (int k8 = 0; k8 < 4; k8++) {
            const int kb = k8 * 8;
            uint32_t af[4][4], bf[8][2];
#pragma unroll
            for (int mt = 0; mt < 4; mt++) {
                const float* ap = As + (wm * 64 + mt * 16 + gid) * TSTRIDE + kb + tig;
                af[mt][0] = __float_as_uint(ap[0]);
                af[mt][1] = __float_as_uint(ap[8 * TSTRIDE]);
                af[mt][2] = __float_as_uint(ap[4]);
                af[mt][3] = __float_as_uint(ap[8 * TSTRIDE + 4]);
            }
#pragma unroll
            for (int nt = 0; nt < 8; nt++) {
                const float* bp = Bs + (wn * 64 + nt * 8 + gid) * TSTRIDE + kb + tig;
                bf[nt][0] = __float_as_uint(bp[0]);
                bf[nt][1] = __float_as_uint(bp[4]);
            }
#pragma unroll
            for (int mt = 0; mt < 4; mt++)
#pragma unroll
                for (int nt = 0; nt < 8; nt++)
                    mma_tf32(acc[mt][nt], af[mt], bf[nt]);
        }
        __syncthreads();                    // done with buf (c&1) before reload
    }

    // Epilogue: c0,c1 -> (row gid, cols 2tig,2tig+1); c2,c3 -> row gid+8.
#pragma unroll
    for (int mt = 0; mt < 4; mt++) {
        int row = m0 + wm * 64 + mt * 16 + gid;
#pragma unroll
        for (int nt = 0; nt < 8; nt++) {
            int col = n0 + wn * 64 + nt * 8 + 2 * tig;
            float2 v0 = make_float2(acc[mt][nt][0], acc[mt][nt][1]);
            float2 v1 = make_float2(acc[mt][nt][2], acc[mt][nt][3]);
            if (BIAS) {
                float2 bb = *(const float2*)(bias + col);
                v0.x += bb.x; v0.y += bb.y;
                v1.x += bb.x; v1.y += bb.y;
            }
            *(float2*)(C + (size_t)row * N + col) = v0;
            *(float2*)(C + (size_t)(row + 8) * N + col) = v1;
        }
    }
}

// ---------------------------------------------------------------------------
// Elementwise tf32 (RNA) rounding
// ---------------------------------------------------------------------------
__global__ void round_tf32_k(const float4* __restrict__ in,
                             float4* __restrict__ out, int n4)
{
    int i = blockIdx.x * blockDim.x + threadIdx.x;
    if (i < n4) {
        float4 v = in[i];
        v.x = rtf32(v.x); v.y = rtf32(v.y);
        v.z = rtf32(v.z); v.w = rtf32(v.w);
        out[i] = v;
    }
}

// ---------------------------------------------------------------------------
// Windowed attention (SIMT fp32; epilogue rounds O to tf32 for GEMM3)
// ---------------------------------------------------------------------------
__global__ __launch_bounds__(256, 1)
void attn_kernel(const float* __restrict__ qk, float* __restrict__ ao)
{
    extern __shared__ float sm[];
    float* Ps = sm;              // 128*256 floats
    float* Kc = sm + 32768;      // 256*64 floats (phase C)
    float* sQ = sm;              // phase A: 32*128 (overlaps Ps region, OK)
    float* sK = sm + 4096;       // phase A: 32*256

    const int tid = threadIdx.x;
    const int b   = blockIdx.x >> 6;
    const int wi  = blockIdx.x & 63;
    const size_t qrow0 = (size_t)b * 8192 + (size_t)wi * 128;
    const bool w0 = (wi == 0);
    const int tr = tid >> 4;
    const int tc = tid & 15;

    float acc[8][16];
#pragma unroll
    for (int i = 0; i < 8; i++)
#pragma unroll
        for (int j = 0; j < 16; j++) acc[i][j] = 0.f;

    // ---- Phase A: S = Q . K2^T over d chunks of 32 ----
    for (int d0 = 0; d0 < 512; d0 += 32) {
#pragma unroll
        for (int l = 0; l < 4; l++) {
            int idx = tid + l * 256;
            int row = idx >> 3;
            int kq  = idx & 7;
            float4 v = *(const float4*)(qk + (qrow0 + row) * 1024 + d0 + kq * 4);
            sQ[(kq * 4 + 0) * 128 + row] = v.x;
            sQ[(kq * 4 + 1) * 128 + row] = v.y;
            sQ[(kq * 4 + 2) * 128 + row] = v.z;
            sQ[(kq * 4 + 3) * 128 + row] = v.w;
        }
#pragma unroll
        for (int l = 0; l < 8; l++) {
            int idx = tid + l * 256;
            int row = idx >> 3;
            int kq  = idx & 7;
            float4 v = make_float4(0.f, 0.f, 0.f, 0.f);
            if (!(w0 && row < 128))
                v = *(const float4*)(qk + (qrow0 + row - 128) * 1024 + 512 + d0 + kq * 4);
            sK[(kq * 4 + 0) * 256 + row] = v.x;
            sK[(kq * 4 + 1) * 256 + row] = v.y;
            sK[(kq * 4 + 2) * 256 + row] = v.z;
            sK[(kq * 4 + 3) * 256 + row] = v.w;
        }
        __syncthreads();
#pragma unroll 8
        for (int kk = 0; kk < 32; kk++) {
            float4 a0 = *(const float4*)&sQ[kk * 128 + tr * 8];
            float4 a1 = *(const float4*)&sQ[kk * 128 + tr * 8 + 4];
            float4 b0 = *(const float4*)&sK[kk * 256 + tc * 16];
            float4 b1 = *(const float4*)&sK[kk * 256 + tc * 16 + 4];
            float4 b2 = *(const float4*)&sK[kk * 256 + tc * 16 + 8];
            float4 b3 = *(const float4*)&sK[kk * 256 + tc * 16 + 12];
            float af[8]  = {a0.x, a0.y, a0.z, a0.w, a1.x, a1.y, a1.z, a1.w};
            float bfv[16] = {b0.x, b0.y, b0.z, b0.w, b1.x, b1.y, b1.z, b1.w,
                             b2.x, b2.y, b2.z, b2.w, b3.x, b3.y, b3.z, b3.w};
#pragma unroll
            for (int i = 0; i < 8; i++)
#pragma unroll
                for (int j = 0; j < 16; j++)
                    acc[i][j] += af[i] * bfv[j];
        }
        __syncthreads();
    }

    // ---- mask + softmax ----
    const float scale = 0.04419417382415922f;   // 512^-0.5
#pragma unroll
    for (int ri = 0; ri < 8; ri++) {
        int i = tr * 8 + ri;
        float mx = -3.402823466e38f;
#pragma unroll
        for (int cj = 0; cj < 16; cj++) {
            int j = tc * 16 + cj;
            float v = acc[ri][cj] * scale;
            if (j > i + 128) v = -3.402823466e38f;
            acc[ri][cj] = v;
            mx = fmaxf(mx, v);
        }
#pragma unroll
        for (int m = 8; m >= 1; m >>= 1)
            mx = fmaxf(mx, __shfl_xor_sync(0xffffffffu, mx, m));
        float sum = 0.f;
#pragma unroll
        for (int cj = 0; cj < 16; cj++) {
            float e = __expf(acc[ri][cj] - mx);
            acc[ri][cj] = e;
            sum += e;
        }
#pragma unroll
        for (int m = 8; m >= 1; m >>= 1)
            sum += __shfl_xor_sync(0xffffffffu, sum, m);
        float inv = 1.f / sum;
#pragma unroll
        for (int cj = 0; cj < 16; cj++)
            Ps[i * 256 + tc * 16 + cj] = acc[ri][cj] * inv;
    }
    __syncthreads();

    // ---- Phase C: O = P . K2 ----
    for (int co = 0; co < 8; co++) {
        int c0 = co * 64;
#pragma unroll
        for (int l = 0; l < 16; l++) {
            int idx = tid + l * 256;
            int row = idx >> 4;
            int cq  = idx & 15;
            float4 v = make_float4(0.f, 0.f, 0.f, 0.f);
            if (!(w0 && row < 128))
                v = *(const float4*)(qk + (qrow0 + row - 128) * 1024 + 512 + c0 + cq * 4);
            *(float4*)&Kc[row * 64 + cq * 4] = v;
        }
        __syncthreads();

        float a2[8][4];
#pragma unroll
        for (int i = 0; i < 8; i++)
#pragma unroll
            for (int j = 0; j < 4; j++) a2[i][j] = 0.f;

#pragma unroll 2
        for (int j4 = 0; j4 < 64; j4++) {
            float4 bv0 = *(const float4*)&Kc[(j4 * 4 + 0) * 64 + tc * 4];
            float4 bv1 = *(const float4*)&Kc[(j4 * 4 + 1) * 64 + tc * 4];
            float4 bv2 = *(const float4*)&Kc[(j4 * 4 + 2) * 64 + tc * 4];
            float4 bv3 = *(const float4*)&Kc[(j4 * 4 + 3) * 64 + tc * 4];
#pragma unroll
            for (int ri = 0; ri < 8; ri++) {
                float4 a = *(const float4*)&Ps[(tr * 8 + ri) * 256 + j4 * 4];
                a2[ri][0] += a.x * bv0.x; a2[ri][1] += a.x * bv0.y;
                a2[ri][2] += a.x * bv0.z; a2[ri][3] += a.x * bv0.w;
                a2[ri][0] += a.y * bv1.x; a2[ri][1] += a.y * bv1.y;
                a2[ri][2] += a.y * bv1.z; a2[ri][3] += a.y * bv1.w;
                a2[ri][0] += a.z * bv2.x; a2[ri][1] += a.z * bv2.y;
                a2[ri][2] += a.z * bv2.z; a2[ri][3] += a.z * bv2.w;
                a2[ri][0] += a.w * bv3.x; a2[ri][1] += a.w * bv3.y;
                a2[ri][2] += a.w * bv3.z; a2[ri][3] += a.w * bv3.w;
            }
        }

#pragma unroll
        for (int ri = 0; ri < 8; ri++) {
            float4 v;
            v.x = rtf32(a2[ri][0]); v.y = rtf32(a2[ri][1]);
            v.z = rtf32(a2[ri][2]); v.w = rtf32(a2[ri][3]);
            *(float4*)(ao + (qrow0 + tr * 8 + ri) * 512 + c0 + tc * 4) = v;
        }
        __syncthreads();
    }
}

// ---------------------------------------------------------------------------
extern "C" void kernel_launch(void* const* d_in, const int* in_sizes, int n_in,
                              void* d_out, int out_size)
{
    (void)in_sizes; (void)n_in; (void)out_size;
    const float* x     = (const float*)d_in[0];   // (4,8192,512)
    const float* w_qkv = (const float*)d_in[1];   // (1536,512); rows 0..1023 used
    const float* w_out = (const float*)d_in[2];   // (512,512)
    const float* b_out = (const float*)d_in[3];   // (512,)
    float* out = (float*)d_out;                   // (4,8192,512)

    float *qk, *ao, *xc, *wc, *wo;
    cudaGetSymbolAddress((void**)&qk, g_qk);
    cudaGetSymbolAddress((void**)&ao, g_ao);
    cudaGetSymbolAddress((void**)&xc, g_xc);
    cudaGetSymbolAddress((void**)&wc, g_wc);
    cudaGetSymbolAddress((void**)&wo, g_wo);

    cudaFuncSetAttribute(attn_kernel,
                         cudaFuncAttributeMaxDynamicSharedMemorySize, 196608);
    cudaFuncSetAttribute(mma_gemm<false>,
                         cudaFuncAttributeMaxDynamicSharedMemorySize, 90112);
    cudaFuncSetAttribute(mma_gemm<true>,
                         cudaFuncAttributeMaxDynamicSharedMemorySize, 90112);

    // 0) Round GEMM operands to tf32 (RNA, unbiased).
    round_tf32_k<<<(4194304 + 255) / 256, 256>>>((const float4*)x, (float4*)xc, 4194304);
    round_tf32_k<<<(131072  + 255) / 256, 256>>>((const float4*)w_qkv, (float4*)wc, 131072);
    round_tf32_k<<<(65536   + 255) / 256, 256>>>((const float4*)w_out, (float4*)wo, 65536);

    // 1) QK projection on tensor cores (V is dead in the reference — skip it).
    {
        dim3 g(1024 / 128, 32768 / 128);
        mma_gemm<false><<<g, 128, 90112>>>(xc, wc, nullptr, qk, 1024, 512);
    }

    // 2) Windowed attention (256 windows).
    attn_kernel<<<256, 256, 196608>>>(qk, ao);

    // 3) Output projection + bias on tensor cores.
    {
        dim3 g(512 / 128, 32768 / 128);
        mma_gemm<true><<<g, 128, 90112>>>(ao, wo, b_out, out, 512, 512);
    }
}

// round 7
// speedup vs baseline: 3.1282x; 1.6327x over previous
#include <cuda_runtime.h>
#include <math.h>
#include <stdint.h>

// ---------------------------------------------------------------------------
// Scratch (no cudaMalloc allowed)
// ---------------------------------------------------------------------------
__device__ float g_qk[33554432];   // 32768 x 1024  (Q | K) tf32-rounded
__device__ float g_ao[16777216];   // 32768 x 512   attention output (tf32-rounded)
__device__ float g_xc[16777216];   // 32768 x 512   x rounded to tf32
__device__ float g_wc[524288];     // 1024 x 512    w_qkv rows 0..1023, tf32-rounded
__device__ float g_wo[262144];     // 512 x 512     w_out, tf32-rounded

__device__ __forceinline__ float rtf32(float v) {  // round-to-nearest tf32
    uint32_t r;
    asm("cvt.rna.tf32.f32 %0, %1;" : "=r"(r) : "f"(v));
    return __uint_as_float(r);
}
__device__ __forceinline__ uint32_t smem_u32(const void* p) {
    uint32_t a;
    asm("{ .reg .u64 t; cvta.to.shared.u64 t, %1; cvt.u32.u64 %0, t; }"
        : "=r"(a) : "l"(p));
    return a;
}
__device__ __forceinline__ void cpa16(uint32_t s, const void* g) {
    asm volatile("cp.async.cg.shared.global [%0], [%1], 16;" :: "r"(s), "l"(g));
}
// Zero-fill variant: src-size 0 -> writes 16 zero bytes, no gmem read.
__device__ __forceinline__ void cpa16z(uint32_t s, const void* g, int sz) {
    asm volatile("cp.async.cg.shared.global [%0], [%1], 16, %2;"
                 :: "r"(s), "l"(g), "r"(sz));
}

// mma.sync m16n8k8 tf32 (baseline PTX, works on .target sm_103)
__device__ __forceinline__ void mma_tf32(float* d, const uint32_t* a,
                                         const uint32_t* b) {
    asm volatile(
        "mma.sync.aligned.m16n8k8.row.col.f32.tf32.tf32.f32 "
        "{%0,%1,%2,%3}, {%4,%5,%6,%7}, {%8,%9}, {%0,%1,%2,%3};"
        : "+f"(d[0]), "+f"(d[1]), "+f"(d[2]), "+f"(d[3])
        : "r"(a[0]), "r"(a[1]), "r"(a[2]), "r"(a[3]), "r"(b[0]), "r"(b[1]));
}

// ---------------------------------------------------------------------------
// tf32 mma.sync GEMM: C[M,N] = A[M,K] @ B[N,K]^T (+bias, optional tf32 round).
// CTA: 128x128 tile, 128 threads = 4 warps (2x2), warp tile 64x64.
// ---------------------------------------------------------------------------
#define TSTRIDE 44

__device__ __forceinline__ void load_tile44(float* dst, const float* gsrc,
                                            int K, int tid) {
#pragma unroll
    for (int l = 0; l < 8; l++) {
        int idx = tid + l * 128;        // 0..1023 (128 rows x 8 x 16B)
        int row = idx >> 3;
        int k16 = idx & 7;
        cpa16(smem_u32(dst + row * TSTRIDE + k16 * 4),
              gsrc + (size_t)row * K + k16 * 4);
    }
}

template<bool BIAS, bool ROUND>
__global__ __launch_bounds__(128)
void mma_gemm(const float* __restrict__ A, const float* __restrict__ B,
              const float* __restrict__ bias, float* __restrict__ C,
              int N, int K)
{
    extern __shared__ float sm[];
    float* Abuf[2] = {sm,          sm + 5632};
    float* Bbuf[2] = {sm + 11264,  sm + 16896};

    const int tid = threadIdx.x;
    const int wid = tid >> 5, lid = tid & 31;
    const int gid = lid >> 2, tig = lid & 3;
    const int wm = wid >> 1, wn = wid & 1;
    const int n0 = blockIdx.x * 128, m0 = blockIdx.y * 128;
    const int NC = K >> 5;

    const float* gA = A + (size_t)m0 * K;
    const float* gB = B + (size_t)n0 * K;

    float acc[4][8][4];
#pragma unroll
    for (int mt = 0; mt < 4; mt++)
#pragma unroll
        for (int nt = 0; nt < 8; nt++)
#pragma unroll
            for (int r = 0; r < 4; r++) acc[mt][nt][r] = 0.f;

    load_tile44(Abuf[0], gA, K, tid);
    load_tile44(Bbuf[0], gB, K, tid);
    asm volatile("cp.async.commit_group;" ::: "memory");

    for (int c = 0; c < NC; c++) {
        if (c + 1 < NC) {
            int nb = (c + 1) & 1;
            load_tile44(Abuf[nb], gA + (c + 1) * 32, K, tid);
            load_tile44(Bbuf[nb], gB + (c + 1) * 32, K, tid);
            asm volatile("cp.async.commit_group;" ::: "memory");
            asm volatile("cp.async.wait_group 1;" ::: "memory");
        } else {
            asm volatile("cp.async.wait_group 0;" ::: "memory");
        }
        __syncthreads();

        const float* As = Abuf[c & 1];
        const float* Bs = Bbuf[c & 1];
#pragma unroll
        for (int k8 = 0; k8 < 4; k8++) {
            const int kb = k8 * 8;
            uint32_t af[4][4], bf[8][2];
#pragma unroll
            for (int mt = 0; mt < 4; mt++) {
                const float* ap = As + (wm * 64 + mt * 16 + gid) * TSTRIDE + kb + tig;
                af[mt][0] = __float_as_uint(ap[0]);
                af[mt][1] = __float_as_uint(ap[8 * TSTRIDE]);
                af[mt][2] = __float_as_uint(ap[4]);
                af[mt][3] = __float_as_uint(ap[8 * TSTRIDE + 4]);
            }
#pragma unroll
            for (int nt = 0; nt < 8; nt++) {
                const float* bp = Bs + (wn * 64 + nt * 8 + gid) * TSTRIDE + kb + tig;
                bf[nt][0] = __float_as_uint(bp[0]);
                bf[nt][1] = __float_as_uint(bp[4]);
            }
#pragma unroll
            for (int mt = 0; mt < 4; mt++)
#pragma unroll
                for (int nt = 0; nt < 8; nt++)
                    mma_tf32(acc[mt][nt], af[mt], bf[nt]);
        }
        __syncthreads();
    }

#pragma unroll
    for (int mt = 0; mt < 4; mt++) {
        int row = m0 + wm * 64 + mt * 16 + gid;
#pragma unroll
        for (int nt = 0; nt < 8; nt++) {
            int col = n0 + wn * 64 + nt * 8 + 2 * tig;
            float2 v0 = make_float2(acc[mt][nt][0], acc[mt][nt][1]);
            float2 v1 = make_float2(acc[mt][nt][2], acc[mt][nt][3]);
            if (BIAS) {
                float2 bb = *(const float2*)(bias + col);
                v0.x += bb.x; v0.y += bb.y;
                v1.x += bb.x; v1.y += bb.y;
            }
            if (ROUND) {
                v0.x = rtf32(v0.x); v0.y = rtf32(v0.y);
                v1.x = rtf32(v1.x); v1.y = rtf32(v1.y);
            }
            *(float2*)(C + (size_t)row * N + col) = v0;
            *(float2*)(C + (size_t)(row + 8) * N + col) = v1;
        }
    }
}

// ---------------------------------------------------------------------------
// Elementwise tf32 (RNA) rounding
// ---------------------------------------------------------------------------
__global__ void round_tf32_k(const float4* __restrict__ in,
                             float4* __restrict__ out, int n4)
{
    int i = blockIdx.x * blockDim.x + threadIdx.x;
    if (i < n4) {
        float4 v = in[i];
        v.x = rtf32(v.x); v.y = rtf32(v.y);
        v.z = rtf32(v.z); v.w = rtf32(v.w);
        out[i] = v;
    }
}

// ---------------------------------------------------------------------------
// Tensor-core windowed attention. One CTA per (batch, window): 256 CTAs,
// 256 threads = 8 warps.
//   Phase A: S[128,256] = Q.K2^T  in registers (warp grid 2x4, tile 64x64),
//            K chunks of 32, double-buffered cp.async (stride-36 smem).
//   Softmax: S -> Ps (stride 260), mask j>i+128, write P tf32-rounded.
//   Phase C: O[128,512] = P.K2 ; per 32-col d-chunk, stage K2^T (Kt, stride
//            260, conflict-free lane-along-j stores), warp grid 4x2 tile 32x16.
// smem: Ps 128x260 + Kt 32x260 = 166400 B (phase-A staging overlaps Ps).
// ---------------------------------------------------------------------------
#define ASTR 36
#define PSTR 260

__global__ __launch_bounds__(256, 1)
void attn_mma(const float* __restrict__ qk, float* __restrict__ ao)
{
    extern __shared__ float sm[];
    float* Ps = sm;                         // 128 x 260
    float* Kt = sm + 33280;                 // 32 x 260
    float* Qb[2] = {sm,         sm + 13824};
    float* Kb[2] = {sm + 4608,  sm + 18432};

    const int tid = threadIdx.x;
    const int wid = tid >> 5, lid = tid & 31;
    const int gid = lid >> 2, tig = lid & 3;
    const int b   = blockIdx.x >> 6;
    const int wi  = blockIdx.x & 63;
    const size_t qrow0 = (size_t)b * 8192 + (size_t)wi * 128;
    const bool w0 = (wi == 0);

    // ---- Phase A: S = Q . K2^T ----
    const int wm = wid >> 2, wn = wid & 3;   // 2x4 warp grid, 64x64 tiles
    float acc[4][8][4];
#pragma unroll
    for (int mt = 0; mt < 4; mt++)
#pragma unroll
        for (int nt = 0; nt < 8; nt++)
#pragma unroll
            for (int r = 0; r < 4; r++) acc[mt][nt][r] = 0.f;

    const float* Qg = qk + qrow0 * 1024;

    // stage chunk c into buffer bi
    auto stage = [&](int c, int bi) {
        float* sQ = Qb[bi];
        float* sK = Kb[bi];
#pragma unroll
        for (int l = 0; l < 4; l++) {
            int idx = tid + l * 256;        // 0..1023: 128 rows x 8
            int row = idx >> 3, q = idx & 7;
            cpa16(smem_u32(sQ + row * ASTR + q * 4),
                  Qg + (size_t)row * 1024 + c * 32 + q * 4);
        }
#pragma unroll
        for (int l = 0; l < 8; l++) {
            int idx = tid + l * 256;        // 0..2047: 256 rows x 8
            int row = idx >> 3, q = idx & 7;
            const float* src = qk + (qrow0 + row - 128) * 1024 + 512 + c * 32 + q * 4;
            int sz = (w0 && row < 128) ? 0 : 16;
            cpa16z(smem_u32(sK + row * ASTR + q * 4), (w0 && row < 128) ? qk : src, sz);
        }
    };

    stage(0, 0);
    asm volatile("cp.async.commit_group;" ::: "memory");

    for (int c = 0; c < 16; c++) {
        if (c + 1 < 16) {
            stage(c + 1, (c + 1) & 1);
            asm volatile("cp.async.commit_group;" ::: "memory");
            asm volatile("cp.async.wait_group 1;" ::: "memory");
        } else {
            asm volatile("cp.async.wait_group 0;" ::: "memory");
        }
        __syncthreads();

        const float* sQ = Qb[c & 1];
        const float* sK = Kb[c & 1];
#pragma unroll
        for (int k8 = 0; k8 < 4; k8++) {
            const int kb = k8 * 8;
            uint32_t af[4][4], bf[8][2];
#pragma unroll
            for (int mt = 0; mt < 4; mt++) {
                const float* ap = sQ + (wm * 64 + mt * 16 + gid) * ASTR + kb + tig;
                af[mt][0] = __float_as_uint(ap[0]);
                af[mt][1] = __float_as_uint(ap[8 * ASTR]);
                af[mt][2] = __float_as_uint(ap[4]);
                af[mt][3] = __float_as_uint(ap[8 * ASTR + 4]);
            }
#pragma unroll
            for (int nt = 0; nt < 8; nt++) {
                const float* bp = sK + (wn * 64 + nt * 8 + gid) * ASTR + kb + tig;
                bf[nt][0] = __float_as_uint(bp[0]);
                bf[nt][1] = __float_as_uint(bp[4]);
            }
#pragma unroll
            for (int mt = 0; mt < 4; mt++)
#pragma unroll
                for (int nt = 0; nt < 8; nt++)
                    mma_tf32(acc[mt][nt], af[mt], bf[nt]);
        }
        __syncthreads();
    }

    // S -> Ps
#pragma unroll
    for (int mt = 0; mt < 4; mt++) {
        int row = wm * 64 + mt * 16 + gid;
#pragma unroll
        for (int nt = 0; nt < 8; nt++) {
            int col = wn * 64 + nt * 8 + 2 * tig;
            *(float2*)(Ps + row * PSTR + col) =
                make_float2(acc[mt][nt][0], acc[mt][nt][1]);
            *(float2*)(Ps + (row + 8) * PSTR + col) =
                make_float2(acc[mt][nt][2], acc[mt][nt][3]);
        }
    }
    __syncthreads();

    // ---- softmax: thread (tr,tc) handles rows tr*8.., cols j = cj*16 + tc ----
    {
        const float scale = 0.04419417382415922f;   // 512^-0.5
        const int tr = tid >> 4, tc = tid & 15;
#pragma unroll
        for (int ri = 0; ri < 8; ri++) {
            int i = tr * 8 + ri;
            float* prow = Ps + i * PSTR;
            float vv[16];
            float mx = -3.402823466e38f;
#pragma unroll
            for (int cj = 0; cj < 16; cj++) {
                int j = cj * 16 + tc;
                float v = prow[j] * scale;
                if (j > i + 128) v = -3.402823466e38f;
                vv[cj] = v;
                mx = fmaxf(mx, v);
            }
#pragma unroll
            for (int m = 8; m >= 1; m >>= 1)
                mx = fmaxf(mx, __shfl_xor_sync(0xffffffffu, mx, m));
            float sum = 0.f;
#pragma unroll
            for (int cj = 0; cj < 16; cj++) {
                vv[cj] = __expf(vv[cj] - mx);
                sum += vv[cj];
            }
#pragma unroll
            for (int m = 8; m >= 1; m >>= 1)
                sum += __shfl_xor_sync(0xffffffffu, sum, m);
            float inv = 1.f / sum;
#pragma unroll
            for (int cj = 0; cj < 16; cj++)
                prow[cj * 16 + tc] = rtf32(vv[cj] * inv);
        }
    }
    __syncthreads();

    // ---- Phase C: O = P . K2, 16 chunks of 32 d-cols ----
    const int wm2 = wid >> 1, wn2 = wid & 1;   // 4x2 warp grid, 32x16 tiles
    for (int co = 0; co < 16; co++) {
        int c0 = co * 32;
        // transpose-stage Kt[d][j]: lane-along-j (conflict-free stores)
#pragma unroll
        for (int l = 0; l < 8; l++) {
            float4 v = make_float4(0.f, 0.f, 0.f, 0.f);
            if (!(w0 && tid < 128))
                v = *(const float4*)(qk + (qrow0 + tid - 128) * 1024 + 512 + c0 + l * 4);
            Kt[(l * 4 + 0) * PSTR + tid] = v.x;
            Kt[(l * 4 + 1) * PSTR + tid] = v.y;
            Kt[(l * 4 + 2) * PSTR + tid] = v.z;
            Kt[(l * 4 + 3) * PSTR + tid] = v.w;
        }
        __syncthreads();

        float a2[2][2][4];
#pragma unroll
        for (int mt = 0; mt < 2; mt++)
#pragma unroll
            for (int nt = 0; nt < 2; nt++)
#pragma unroll
                for (int r = 0; r < 4; r++) a2[mt][nt][r] = 0.f;

#pragma unroll 4
        for (int kb = 0; kb < 256; kb += 8) {
            uint32_t af[2][4], bf[2][2];
#pragma unroll
            for (int mt = 0; mt < 2; mt++) {
                const float* ap = Ps + (wm2 * 32 + mt * 16 + gid) * PSTR + kb + tig;
                af[mt][0] = __float_as_uint(ap[0]);
                af[mt][1] = __float_as_uint(ap[8 * PSTR]);
                af[mt][2] = __float_as_uint(ap[4]);
                af[mt][3] = __float_as_uint(ap[8 * PSTR + 4]);
            }
#pragma unroll
            for (int nt = 0; nt < 2; nt++) {
                const float* bp = Kt + (wn2 * 16 + nt * 8 + gid) * PSTR + kb + tig;
                bf[nt][0] = __float_as_uint(bp[0]);
                bf[nt][1] = __float_as_uint(bp[4]);
            }
#pragma unroll
            for (int mt = 0; mt < 2; mt++)
#pragma unroll
                for (int nt = 0; nt < 2; nt++)
                    mma_tf32(a2[mt][nt], af[mt], bf[nt]);
        }

#pragma unroll
        for (int mt = 0; mt < 2; mt++) {
            size_t row = qrow0 + wm2 * 32 + mt * 16 + gid;
#pragma unroll
            for (int nt = 0; nt < 2; nt++) {
                int col = c0 + wn2 * 16 + nt * 8 + 2 * tig;
                *(float2*)(ao + row * 512 + col) =
                    make_float2(rtf32(a2[mt][nt][0]), rtf32(a2[mt][nt][1]));
                *(float2*)(ao + (row + 8) * 512 + col) =
                    make_float2(rtf32(a2[mt][nt][2]), rtf32(a2[mt][nt][3]));
            }
        }
        __syncthreads();
    }
}

// ---------------------------------------------------------------------------
extern "C" void kernel_launch(void* const* d_in, const int* in_sizes, int n_in,
                              void* d_out, int out_size)
{
    (void)in_sizes; (void)n_in; (void)out_size;
    const float* x     = (const float*)d_in[0];   // (4,8192,512)
    const float* w_qkv = (const float*)d_in[1];   // (1536,512); rows 0..1023 used
    const float* w_out = (const float*)d_in[2];   // (512,512)
    const float* b_out = (const float*)d_in[3];   // (512,)
    float* out = (float*)d_out;                   // (4,8192,512)

    float *qk, *ao, *xc, *wc, *wo;
    cudaGetSymbolAddress((void**)&qk, g_qk);
    cudaGetSymbolAddress((void**)&ao, g_ao);
    cudaGetSymbolAddress((void**)&xc, g_xc);
    cudaGetSymbolAddress((void**)&wc, g_wc);
    cudaGetSymbolAddress((void**)&wo, g_wo);

    cudaFuncSetAttribute(attn_mma,
                         cudaFuncAttributeMaxDynamicSharedMemorySize, 166400);
    cudaFuncSetAttribute((const void*)mma_gemm<false, true>,
                         cudaFuncAttributeMaxDynamicSharedMemorySize, 90112);
    cudaFuncSetAttribute((const void*)mma_gemm<true, false>,
                         cudaFuncAttributeMaxDynamicSharedMemorySize, 90112);

    // 0) Round GEMM operands to tf32 (RNA, unbiased).
    round_tf32_k<<<(4194304 + 255) / 256, 256>>>((const float4*)x, (float4*)xc, 4194304);
    round_tf32_k<<<(131072  + 255) / 256, 256>>>((const float4*)w_qkv, (float4*)wc, 131072);
    round_tf32_k<<<(65536   + 255) / 256, 256>>>((const float4*)w_out, (float4*)wo, 65536);

    // 1) QK projection; epilogue rounds to tf32 for the attention MMAs.
    {
        dim3 g(1024 / 128, 32768 / 128);
        mma_gemm<false, true><<<g, 128, 90112>>>(xc, wc, nullptr, qk, 1024, 512);
    }

    // 2) Tensor-core windowed attention (256 windows).
    attn_mma<<<256, 256, 166400>>>(qk, ao);

    // 3) Output projection + bias.
    {
        dim3 g(512 / 128, 32768 / 128);
        mma_gemm<true, false><<<g, 128, 90112>>>(ao, wo, b_out, out, 512, 512);
    }
}